// round 1
// baseline (speedup 1.0000x reference)
#include <cuda_runtime.h>
#include <math.h>

#define NN 50000
#define NE 400000

// ---------------- device scratch (no allocations allowed) ----------------
__device__ float g_feat[(size_t)NN * 484];   // GEMM output of current layer
__device__ float g_x[(size_t)NN * 256];      // node features after ELU
__device__ float g_el[NN * 4];
__device__ float g_er[NN * 4];
__device__ float g_ealpha[(size_t)NE * 4];   // unnormalized softmax numerators per CSR edge
__device__ int   g_deg[NN];
__device__ int   g_wp[NN];
__device__ int   g_rowptr[NN + 1];
__device__ int   g_col[NE];                  // src of edges sorted by dst (CSR)

// ---------------- CSR build ----------------
__global__ void zero_deg_k(int* deg) {
    int i = blockIdx.x * blockDim.x + threadIdx.x;
    if (i < NN) deg[i] = 0;
}

__global__ void hist_k(const int* __restrict__ dst, int* deg) {
    for (int e = blockIdx.x * blockDim.x + threadIdx.x; e < NE; e += gridDim.x * blockDim.x)
        atomicAdd(&deg[dst[e]], 1);
}

__global__ void scan_k(const int* __restrict__ deg, int* rowptr, int* wp) {
    __shared__ int sm[32];
    __shared__ int s_carry;
    int t = threadIdx.x, lane = t & 31, wid = t >> 5;
    if (t == 0) s_carry = 0;
    __syncthreads();
    for (int base = 0; base < NN; base += 1024) {
        int i = base + t;
        int v = (i < NN) ? deg[i] : 0;
        int x = v;
#pragma unroll
        for (int o = 1; o < 32; o <<= 1) {
            int y = __shfl_up_sync(0xffffffffu, x, o);
            if (lane >= o) x += y;
        }
        if (lane == 31) sm[wid] = x;
        __syncthreads();
        if (wid == 0) {
            int s2 = sm[lane];
#pragma unroll
            for (int o = 1; o < 32; o <<= 1) {
                int y = __shfl_up_sync(0xffffffffu, s2, o);
                if (lane >= o) s2 += y;
            }
            sm[lane] = s2;
        }
        __syncthreads();
        int off = wid ? sm[wid - 1] : 0;
        int total = sm[31];
        int excl = x - v + off + s_carry;
        if (i < NN) { rowptr[i] = excl; wp[i] = excl; }
        __syncthreads();
        if (t == 0) s_carry += total;
        __syncthreads();
    }
    if (t == 0) rowptr[NN] = s_carry;
}

__global__ void scatter_k(const int* __restrict__ src, const int* __restrict__ dst,
                          int* wp, int* col) {
    for (int e = blockIdx.x * blockDim.x + threadIdx.x; e < NE; e += gridDim.x * blockDim.x) {
        int p = atomicAdd(&wp[dst[e]], 1);
        col[p] = src[e];
    }
}

// ---------------- fp32 tiled GEMM: C[NR,M] = A[NR,K] @ B[K,M] ----------------
#define BM 128
#define BN 64
#define BKK 16

__global__ __launch_bounds__(256) void gemm_k(const float* __restrict__ A,
                                              const float* __restrict__ B,
                                              float* __restrict__ C,
                                              int NR, int K, int M) {
    __shared__ float As[BKK][BM + 1];
    __shared__ float Bs[BKK][BN];
    int tid = threadIdx.x;
    int row0 = blockIdx.y * BM, col0 = blockIdx.x * BN;
    int tx = tid & 15, ty = tid >> 4;  // tx: 16 col groups of 4, ty: 16 row groups of 8
    float acc[8][4];
#pragma unroll
    for (int i = 0; i < 8; i++)
#pragma unroll
        for (int j = 0; j < 4; j++) acc[i][j] = 0.f;

    for (int k0 = 0; k0 < K; k0 += BKK) {
#pragma unroll
        for (int i = 0; i < 8; i++) {
            int r = (tid >> 4) + 16 * i;
            int gr = row0 + r;
            As[tid & 15][r] = (gr < NR) ? A[(size_t)gr * K + k0 + (tid & 15)] : 0.f;
        }
#pragma unroll
        for (int i = 0; i < 4; i++) {
            int k = (tid >> 6) + 4 * i;
            int gc = col0 + (tid & 63);
            Bs[k][tid & 63] = (gc < M) ? B[(size_t)(k0 + k) * M + gc] : 0.f;
        }
        __syncthreads();
#pragma unroll
        for (int kk = 0; kk < BKK; kk++) {
            float ra[8], rb[4];
#pragma unroll
            for (int i = 0; i < 8; i++) ra[i] = As[kk][ty * 8 + i];
#pragma unroll
            for (int j = 0; j < 4; j++) rb[j] = Bs[kk][tx * 4 + j];
#pragma unroll
            for (int i = 0; i < 8; i++)
#pragma unroll
                for (int j = 0; j < 4; j++) acc[i][j] = fmaf(ra[i], rb[j], acc[i][j]);
        }
        __syncthreads();
    }
#pragma unroll
    for (int i = 0; i < 8; i++) {
        int gr = row0 + ty * 8 + i;
        if (gr < NR) {
#pragma unroll
            for (int j = 0; j < 4; j++) {
                int gc = col0 + tx * 4 + j;
                if (gc < M) C[(size_t)gr * M + gc] = acc[i][j];
            }
        }
    }
}

// ---------------- el/er projections: warp per node ----------------
template <int HD, int D>
__global__ void eler_k(const float* __restrict__ feat, const float* __restrict__ al,
                       const float* __restrict__ ar, float* __restrict__ el,
                       float* __restrict__ er) {
    int w = (blockIdx.x * blockDim.x + threadIdx.x) >> 5;
    int lane = threadIdx.x & 31;
    if (w >= NN) return;
    const float* f = feat + (size_t)w * HD;
    float a0 = 0, a1 = 0, a2 = 0, a3 = 0, b0 = 0, b1 = 0, b2 = 0, b3 = 0;
    constexpr int P = (HD + 31) / 32;
#pragma unroll
    for (int p = 0; p < P; p++) {
        int idx = lane + 32 * p;
        if ((HD % 32 == 0) || idx < HD) {
            float v = f[idx];
            float pl = v * al[idx];
            float pr = v * ar[idx];
            int h = (D % 32 == 0) ? ((32 * p) / D) : (idx / D);
            if (h == 0)      { a0 += pl; b0 += pr; }
            else if (h == 1) { a1 += pl; b1 += pr; }
            else if (h == 2) { a2 += pl; b2 += pr; }
            else             { a3 += pl; b3 += pr; }
        }
    }
#pragma unroll
    for (int o = 16; o; o >>= 1) {
        a0 += __shfl_xor_sync(0xffffffffu, a0, o);
        a1 += __shfl_xor_sync(0xffffffffu, a1, o);
        a2 += __shfl_xor_sync(0xffffffffu, a2, o);
        a3 += __shfl_xor_sync(0xffffffffu, a3, o);
        b0 += __shfl_xor_sync(0xffffffffu, b0, o);
        b1 += __shfl_xor_sync(0xffffffffu, b1, o);
        b2 += __shfl_xor_sync(0xffffffffu, b2, o);
        b3 += __shfl_xor_sync(0xffffffffu, b3, o);
    }
    if (lane == 0) {
        el[w * 4 + 0] = a0; el[w * 4 + 1] = a1; el[w * 4 + 2] = a2; el[w * 4 + 3] = a3;
        er[w * 4 + 0] = b0; er[w * 4 + 1] = b1; er[w * 4 + 2] = b2; er[w * 4 + 3] = b3;
    }
}

__device__ __forceinline__ float lrelu(float e) { return e > 0.f ? e : 0.2f * e; }

// ---------------- aggregate layers 1/2: warp per node, H=4, D=64, ELU ----------------
__global__ void aggregate_h64_k(const float* __restrict__ feat,
                                const int* __restrict__ rowptr, const int* __restrict__ col,
                                const float* __restrict__ el, const float* __restrict__ er,
                                float* __restrict__ ealpha, float* __restrict__ out) {
    int n = (blockIdx.x * blockDim.x + threadIdx.x) >> 5;
    int lane = threadIdx.x & 31;
    if (n >= NN) return;
    int beg = rowptr[n], end = rowptr[n + 1];
    float er0 = er[n * 4 + 0], er1 = er[n * 4 + 1], er2 = er[n * 4 + 2], er3 = er[n * 4 + 3];
    float m0 = -INFINITY, m1 = -INFINITY, m2 = -INFINITY, m3 = -INFINITY;
    for (int j = beg + lane; j < end; j += 32) {
        int s = col[j];
        m0 = fmaxf(m0, lrelu(el[s * 4 + 0] + er0));
        m1 = fmaxf(m1, lrelu(el[s * 4 + 1] + er1));
        m2 = fmaxf(m2, lrelu(el[s * 4 + 2] + er2));
        m3 = fmaxf(m3, lrelu(el[s * 4 + 3] + er3));
    }
#pragma unroll
    for (int o = 16; o; o >>= 1) {
        m0 = fmaxf(m0, __shfl_xor_sync(0xffffffffu, m0, o));
        m1 = fmaxf(m1, __shfl_xor_sync(0xffffffffu, m1, o));
        m2 = fmaxf(m2, __shfl_xor_sync(0xffffffffu, m2, o));
        m3 = fmaxf(m3, __shfl_xor_sync(0xffffffffu, m3, o));
    }
    float s0 = 0, s1 = 0, s2 = 0, s3 = 0;
    for (int j = beg + lane; j < end; j += 32) {
        int s = col[j];
        float x0 = __expf(lrelu(el[s * 4 + 0] + er0) - m0);
        float x1 = __expf(lrelu(el[s * 4 + 1] + er1) - m1);
        float x2 = __expf(lrelu(el[s * 4 + 2] + er2) - m2);
        float x3 = __expf(lrelu(el[s * 4 + 3] + er3) - m3);
        ealpha[j * 4 + 0] = x0; ealpha[j * 4 + 1] = x1;
        ealpha[j * 4 + 2] = x2; ealpha[j * 4 + 3] = x3;
        s0 += x0; s1 += x1; s2 += x2; s3 += x3;
    }
#pragma unroll
    for (int o = 16; o; o >>= 1) {
        s0 += __shfl_xor_sync(0xffffffffu, s0, o);
        s1 += __shfl_xor_sync(0xffffffffu, s1, o);
        s2 += __shfl_xor_sync(0xffffffffu, s2, o);
        s3 += __shfl_xor_sync(0xffffffffu, s3, o);
    }
    float i0 = s0 > 0.f ? 1.f / s0 : 0.f;
    float i1 = s1 > 0.f ? 1.f / s1 : 0.f;
    float i2 = s2 > 0.f ? 1.f / s2 : 0.f;
    float i3 = s3 > 0.f ? 1.f / s3 : 0.f;
    float acc[8];
#pragma unroll
    for (int p = 0; p < 8; p++) acc[p] = 0.f;
    for (int j = beg; j < end; j++) {
        int s = col[j];  // uniform across warp
        const float* f = feat + (size_t)s * 256;
        float a0 = ealpha[j * 4 + 0] * i0;
        float a1 = ealpha[j * 4 + 1] * i1;
        float a2 = ealpha[j * 4 + 2] * i2;
        float a3 = ealpha[j * 4 + 3] * i3;
        acc[0] = fmaf(a0, f[lane +   0], acc[0]);
        acc[1] = fmaf(a0, f[lane +  32], acc[1]);
        acc[2] = fmaf(a1, f[lane +  64], acc[2]);
        acc[3] = fmaf(a1, f[lane +  96], acc[3]);
        acc[4] = fmaf(a2, f[lane + 128], acc[4]);
        acc[5] = fmaf(a2, f[lane + 160], acc[5]);
        acc[6] = fmaf(a3, f[lane + 192], acc[6]);
        acc[7] = fmaf(a3, f[lane + 224], acc[7]);
    }
#pragma unroll
    for (int p = 0; p < 8; p++) {
        float v = acc[p];
        v = v > 0.f ? v : (__expf(v) - 1.f);  // ELU
        out[(size_t)n * 256 + lane + 32 * p] = v;
    }
}

// ---------------- aggregate output layer: H=4, D=121, mean over heads ----------------
__global__ void aggregate_out_k(const float* __restrict__ feat,
                                const int* __restrict__ rowptr, const int* __restrict__ col,
                                const float* __restrict__ el, const float* __restrict__ er,
                                float* __restrict__ ealpha, float* __restrict__ out) {
    int n = (blockIdx.x * blockDim.x + threadIdx.x) >> 5;
    int lane = threadIdx.x & 31;
    if (n >= NN) return;
    int beg = rowptr[n], end = rowptr[n + 1];
    float er0 = er[n * 4 + 0], er1 = er[n * 4 + 1], er2 = er[n * 4 + 2], er3 = er[n * 4 + 3];
    float m0 = -INFINITY, m1 = -INFINITY, m2 = -INFINITY, m3 = -INFINITY;
    for (int j = beg + lane; j < end; j += 32) {
        int s = col[j];
        m0 = fmaxf(m0, lrelu(el[s * 4 + 0] + er0));
        m1 = fmaxf(m1, lrelu(el[s * 4 + 1] + er1));
        m2 = fmaxf(m2, lrelu(el[s * 4 + 2] + er2));
        m3 = fmaxf(m3, lrelu(el[s * 4 + 3] + er3));
    }
#pragma unroll
    for (int o = 16; o; o >>= 1) {
        m0 = fmaxf(m0, __shfl_xor_sync(0xffffffffu, m0, o));
        m1 = fmaxf(m1, __shfl_xor_sync(0xffffffffu, m1, o));
        m2 = fmaxf(m2, __shfl_xor_sync(0xffffffffu, m2, o));
        m3 = fmaxf(m3, __shfl_xor_sync(0xffffffffu, m3, o));
    }
    float s0 = 0, s1 = 0, s2 = 0, s3 = 0;
    for (int j = beg + lane; j < end; j += 32) {
        int s = col[j];
        float x0 = __expf(lrelu(el[s * 4 + 0] + er0) - m0);
        float x1 = __expf(lrelu(el[s * 4 + 1] + er1) - m1);
        float x2 = __expf(lrelu(el[s * 4 + 2] + er2) - m2);
        float x3 = __expf(lrelu(el[s * 4 + 3] + er3) - m3);
        ealpha[j * 4 + 0] = x0; ealpha[j * 4 + 1] = x1;
        ealpha[j * 4 + 2] = x2; ealpha[j * 4 + 3] = x3;
        s0 += x0; s1 += x1; s2 += x2; s3 += x3;
    }
#pragma unroll
    for (int o = 16; o; o >>= 1) {
        s0 += __shfl_xor_sync(0xffffffffu, s0, o);
        s1 += __shfl_xor_sync(0xffffffffu, s1, o);
        s2 += __shfl_xor_sync(0xffffffffu, s2, o);
        s3 += __shfl_xor_sync(0xffffffffu, s3, o);
    }
    float i0 = s0 > 0.f ? 1.f / s0 : 0.f;
    float i1 = s1 > 0.f ? 1.f / s1 : 0.f;
    float i2 = s2 > 0.f ? 1.f / s2 : 0.f;
    float i3 = s3 > 0.f ? 1.f / s3 : 0.f;
    float acc0 = 0, acc1 = 0, acc2 = 0, acc3 = 0;
    int c0 = lane, c1 = lane + 32, c2 = lane + 64, c3 = lane + 96;
    for (int j = beg; j < end; j++) {
        int s = col[j];  // uniform across warp
        const float* f = feat + (size_t)s * 484;
        float a0 = ealpha[j * 4 + 0] * i0;
        float a1 = ealpha[j * 4 + 1] * i1;
        float a2 = ealpha[j * 4 + 2] * i2;
        float a3 = ealpha[j * 4 + 3] * i3;
#pragma unroll
        for (int h = 0; h < 4; h++) {
            float ah = (h == 0) ? a0 : (h == 1) ? a1 : (h == 2) ? a2 : a3;
            const float* fh = f + h * 121;
            acc0 = fmaf(ah, fh[c0], acc0);
            acc1 = fmaf(ah, fh[c1], acc1);
            acc2 = fmaf(ah, fh[c2], acc2);
            if (c3 < 121) acc3 = fmaf(ah, fh[c3], acc3);
        }
    }
    out[(size_t)n * 121 + c0] = acc0 * 0.25f;
    out[(size_t)n * 121 + c1] = acc1 * 0.25f;
    out[(size_t)n * 121 + c2] = acc2 * 0.25f;
    if (c3 < 121) out[(size_t)n * 121 + c3] = acc3 * 0.25f;
}

// ---------------- host launch ----------------
extern "C" void kernel_launch(void* const* d_in, const int* in_sizes, int n_in,
                              void* d_out, int out_size) {
    const float* h   = (const float*)d_in[0];
    const int*   src = (const int*)d_in[1];
    const int*   dst = (const int*)d_in[2];
    const float* W1  = (const float*)d_in[3];
    const float* al1 = (const float*)d_in[4];
    const float* ar1 = (const float*)d_in[5];
    const float* W2  = (const float*)d_in[6];
    const float* al2 = (const float*)d_in[7];
    const float* ar2 = (const float*)d_in[8];
    const float* W3  = (const float*)d_in[9];
    const float* al3 = (const float*)d_in[10];
    const float* ar3 = (const float*)d_in[11];
    float* out = (float*)d_out;

    float *feat, *x, *el, *er, *ealpha;
    int *deg, *wp, *rowptr, *col;
    cudaGetSymbolAddress((void**)&feat,   g_feat);
    cudaGetSymbolAddress((void**)&x,      g_x);
    cudaGetSymbolAddress((void**)&el,     g_el);
    cudaGetSymbolAddress((void**)&er,     g_er);
    cudaGetSymbolAddress((void**)&ealpha, g_ealpha);
    cudaGetSymbolAddress((void**)&deg,    g_deg);
    cudaGetSymbolAddress((void**)&wp,     g_wp);
    cudaGetSymbolAddress((void**)&rowptr, g_rowptr);
    cudaGetSymbolAddress((void**)&col,    g_col);

    // CSR build (graph is identical for all 3 layers)
    zero_deg_k<<<(NN + 255) / 256, 256>>>(deg);
    hist_k<<<512, 256>>>(dst, deg);
    scan_k<<<1, 1024>>>(deg, rowptr, wp);
    scatter_k<<<512, 256>>>(src, dst, wp, col);

    int wblocks = (NN + 7) / 8;  // warp per node, 8 warps per block

    // layer 1
    dim3 g1(4, (NN + BM - 1) / BM);
    gemm_k<<<g1, 256>>>(h, W1, feat, NN, 256, 256);
    eler_k<256, 64><<<wblocks, 256>>>(feat, al1, ar1, el, er);
    aggregate_h64_k<<<wblocks, 256>>>(feat, rowptr, col, el, er, ealpha, x);

    // layer 2
    gemm_k<<<g1, 256>>>(x, W2, feat, NN, 256, 256);
    eler_k<256, 64><<<wblocks, 256>>>(feat, al2, ar2, el, er);
    aggregate_h64_k<<<wblocks, 256>>>(feat, rowptr, col, el, er, ealpha, x);

    // layer 3 (output): M = 4*121 = 484
    dim3 g3((484 + BN - 1) / BN, (NN + BM - 1) / BM);
    gemm_k<<<g3, 256>>>(x, W3, feat, NN, 256, 484);
    eler_k<484, 121><<<wblocks, 256>>>(feat, al3, ar3, el, er);
    aggregate_out_k<<<wblocks, 256>>>(feat, rowptr, col, el, er, ealpha, out);
}

// round 5
// speedup vs baseline: 1.3266x; 1.3266x over previous
#include <cuda_runtime.h>
#include <cuda_bf16.h>
#include <math.h>
#include <stdint.h>

#define NN 50000
#define NE 400000

// ---------------- device scratch (no allocations allowed) ----------------
__device__ float g_feat[(size_t)NN * 484];   // GEMM output of current layer (fp32)
__device__ float g_x[(size_t)NN * 256];      // node features after ELU
__device__ float g_el[NN * 4];
__device__ float g_er[NN * 4];
__device__ float g_ealpha[(size_t)NE * 4];
__device__ int   g_deg[NN];
__device__ int   g_wp[NN];
__device__ int   g_rowptr[NN + 1];
__device__ int   g_col[NE];
// bf16 split-precision operands
__device__ __nv_bfloat16 g_ah[(size_t)NN * 256];
__device__ __nv_bfloat16 g_al[(size_t)NN * 256];
__device__ __nv_bfloat16 g_bh[512 * 256];
__device__ __nv_bfloat16 g_bl[512 * 256];

// ---------------- warp-MMA helpers (sm_80-era, legal at compute_103) ----------------
__device__ __forceinline__ uint32_t smem_u32(const void* p) {
    uint32_t a;
    asm("{ .reg .u64 t; cvta.to.shared.u64 t, %1; cvt.u32.u64 %0, t; }" : "=r"(a) : "l"(p));
    return a;
}
__device__ __forceinline__ void ldsm_x4(uint32_t& r0, uint32_t& r1, uint32_t& r2, uint32_t& r3,
                                        uint32_t addr) {
    asm volatile("ldmatrix.sync.aligned.m8n8.x4.shared.b16 {%0,%1,%2,%3}, [%4];"
                 : "=r"(r0), "=r"(r1), "=r"(r2), "=r"(r3) : "r"(addr));
}
__device__ __forceinline__ void mma_bf16(float* c, const uint32_t* a, const uint32_t* b) {
    asm volatile("mma.sync.aligned.m16n8k16.row.col.f32.bf16.bf16.f32 "
                 "{%0,%1,%2,%3},{%4,%5,%6,%7},{%8,%9},{%0,%1,%2,%3};"
                 : "+f"(c[0]), "+f"(c[1]), "+f"(c[2]), "+f"(c[3])
                 : "r"(a[0]), "r"(a[1]), "r"(a[2]), "r"(a[3]), "r"(b[0]), "r"(b[1]));
}

// ---------------- CSR build ----------------
__global__ void zero_deg_k(int* deg) {
    int i = blockIdx.x * blockDim.x + threadIdx.x;
    if (i < NN) deg[i] = 0;
}

__global__ void hist_k(const int* __restrict__ dst, int* deg) {
    for (int e = blockIdx.x * blockDim.x + threadIdx.x; e < NE; e += gridDim.x * blockDim.x)
        atomicAdd(&deg[dst[e]], 1);
}

__global__ void scan_k(const int* __restrict__ deg, int* rowptr, int* wp) {
    __shared__ int sm[32];
    __shared__ int s_carry;
    int t = threadIdx.x, lane = t & 31, wid = t >> 5;
    if (t == 0) s_carry = 0;
    __syncthreads();
    for (int base = 0; base < NN; base += 1024) {
        int i = base + t;
        int v = (i < NN) ? deg[i] : 0;
        int x = v;
#pragma unroll
        for (int o = 1; o < 32; o <<= 1) {
            int y = __shfl_up_sync(0xffffffffu, x, o);
            if (lane >= o) x += y;
        }
        if (lane == 31) sm[wid] = x;
        __syncthreads();
        if (wid == 0) {
            int s2 = sm[lane];
#pragma unroll
            for (int o = 1; o < 32; o <<= 1) {
                int y = __shfl_up_sync(0xffffffffu, s2, o);
                if (lane >= o) s2 += y;
            }
            sm[lane] = s2;
        }
        __syncthreads();
        int off = wid ? sm[wid - 1] : 0;
        int total = sm[31];
        int excl = x - v + off + s_carry;
        if (i < NN) { rowptr[i] = excl; wp[i] = excl; }
        __syncthreads();
        if (t == 0) s_carry += total;
        __syncthreads();
    }
    if (t == 0) rowptr[NN] = s_carry;
}

__global__ void scatter_k(const int* __restrict__ src, const int* __restrict__ dst,
                          int* wp, int* col) {
    for (int e = blockIdx.x * blockDim.x + threadIdx.x; e < NE; e += gridDim.x * blockDim.x) {
        int p = atomicAdd(&wp[dst[e]], 1);
        col[p] = src[e];
    }
}

// ---------------- bf16 split conversion ----------------
__global__ void cvt_a_k(const float* __restrict__ x, __nv_bfloat16* __restrict__ hi,
                        __nv_bfloat16* __restrict__ lo, int total) {
    int i = blockIdx.x * blockDim.x + threadIdx.x;
    if (i < total) {
        float v = x[i];
        __nv_bfloat16 h = __float2bfloat16(v);
        hi[i] = h;
        lo[i] = __float2bfloat16(v - __bfloat162float(h));
    }
}

// W [256, Mreal] row-major -> transposed bf16 hi/lo [Npad, 256], zero-padded rows
__global__ void cvt_w_k(const float* __restrict__ W, __nv_bfloat16* __restrict__ hiT,
                        __nv_bfloat16* __restrict__ loT, int Mreal, int Npad) {
    int i = blockIdx.x * blockDim.x + threadIdx.x;
    if (i >= Npad * 256) return;
    int n = i >> 8, k = i & 255;
    float v = (n < Mreal) ? W[k * Mreal + n] : 0.f;
    __nv_bfloat16 h = __float2bfloat16(v);
    hiT[i] = h;
    loT[i] = __float2bfloat16(v - __bfloat162float(h));
}

// ---------------- HMMA bf16x3 GEMM: C[NN,M] = A[NN,256] @ W[256,M] ----------------
// CTA tile 128x128, 8 warps (4M x 2N), warp tile 32x64, K-chunk 32.
// smem rows padded to 40 bf16 (80 B): 16B-aligned ldmatrix rows, conflict-free.
#define SROW 40

__global__ void __launch_bounds__(256) gemm_hmma_k(
    const __nv_bfloat16* __restrict__ ah, const __nv_bfloat16* __restrict__ al,
    const __nv_bfloat16* __restrict__ bh, const __nv_bfloat16* __restrict__ bl,
    float* __restrict__ C, int M) {
    __shared__ __nv_bfloat16 sAh[128][SROW];
    __shared__ __nv_bfloat16 sAl[128][SROW];
    __shared__ __nv_bfloat16 sBh[128][SROW];
    __shared__ __nv_bfloat16 sBl[128][SROW];

    int tid = threadIdx.x, lane = tid & 31, wid = tid >> 5;
    int warp_m = wid & 3, warp_n = wid >> 2;
    int m0 = blockIdx.y * 128, n0 = blockIdx.x * 128;

    float acc[2][8][4];
#pragma unroll
    for (int mb = 0; mb < 2; mb++)
#pragma unroll
        for (int nb = 0; nb < 8; nb++)
#pragma unroll
            for (int q = 0; q < 4; q++) acc[mb][nb][q] = 0.f;

    // ldmatrix per-thread byte offsets (within a tile), precomputed
    // A frag (x4): lanes 0-15 -> rows (lane&15), col half = lane>>4 (k 0-7 / 8-15)
    uint32_t sa_h = smem_u32(sAh), sa_l = smem_u32(sAl);
    uint32_t sb_h = smem_u32(sBh), sb_l = smem_u32(sBl);
    int arow = warp_m * 32 + (lane & 15);
    uint32_t aoff[2];
    aoff[0] = (uint32_t)(arow * (SROW * 2) + (lane >> 4) * 16);
    aoff[1] = (uint32_t)((arow + 16) * (SROW * 2) + (lane >> 4) * 16);
    // B frag (x4 fetches 2 n-blocks): rows n = base + (lane&7) + (lane>=16 ? 8 : 0),
    // col half = (lane>>3)&1
    int brow_in = (lane & 7) + ((lane >> 4) & 1) * 8;
    uint32_t boff[4];
#pragma unroll
    for (int p = 0; p < 4; p++)
        boff[p] = (uint32_t)((warp_n * 64 + p * 16 + brow_in) * (SROW * 2) + ((lane >> 3) & 1) * 16);

    const uint4 zero4 = make_uint4(0, 0, 0, 0);

    for (int kc = 0; kc < 256; kc += 32) {
        // ---- stage tiles: 128 rows x 32 bf16 each (512 uint4 per tile) ----
#pragma unroll
        for (int i = 0; i < 2; i++) {
            int e = tid + 256 * i;           // 0..511
            int row = e >> 2, q = e & 3;     // q: 16B chunk (8 bf16)
            int arow_g = m0 + row;
            uint4 vh = zero4, vl = zero4;
            if (arow_g < NN) {
                size_t off = (size_t)arow_g * 256 + kc + q * 8;
                vh = *reinterpret_cast<const uint4*>(ah + off);
                vl = *reinterpret_cast<const uint4*>(al + off);
            }
            *reinterpret_cast<uint4*>(&sAh[row][q * 8]) = vh;
            *reinterpret_cast<uint4*>(&sAl[row][q * 8]) = vl;
            size_t boffg = (size_t)(n0 + row) * 256 + kc + q * 8;
            *reinterpret_cast<uint4*>(&sBh[row][q * 8]) = *reinterpret_cast<const uint4*>(bh + boffg);
            *reinterpret_cast<uint4*>(&sBl[row][q * 8]) = *reinterpret_cast<const uint4*>(bl + boffg);
        }
        __syncthreads();

#pragma unroll
        for (int ks = 0; ks < 2; ks++) {
            uint32_t kb = (uint32_t)(ks * 32);   // 16 bf16 = 32 bytes
            uint32_t ahf[2][4], alf[2][4], bfr[8][2];
#pragma unroll
            for (int mb = 0; mb < 2; mb++) {
                ldsm_x4(ahf[mb][0], ahf[mb][1], ahf[mb][2], ahf[mb][3], sa_h + aoff[mb] + kb);
                ldsm_x4(alf[mb][0], alf[mb][1], alf[mb][2], alf[mb][3], sa_l + aoff[mb] + kb);
            }
            // B_hi fragments
#pragma unroll
            for (int p = 0; p < 4; p++)
                ldsm_x4(bfr[2 * p][0], bfr[2 * p][1], bfr[2 * p + 1][0], bfr[2 * p + 1][1],
                        sb_h + boff[p] + kb);
#pragma unroll
            for (int mb = 0; mb < 2; mb++)
#pragma unroll
                for (int nb = 0; nb < 8; nb++) mma_bf16(acc[mb][nb], ahf[mb], bfr[nb]);
#pragma unroll
            for (int mb = 0; mb < 2; mb++)
#pragma unroll
                for (int nb = 0; nb < 8; nb++) mma_bf16(acc[mb][nb], alf[mb], bfr[nb]);
            // B_lo fragments (reuse regs)
#pragma unroll
            for (int p = 0; p < 4; p++)
                ldsm_x4(bfr[2 * p][0], bfr[2 * p][1], bfr[2 * p + 1][0], bfr[2 * p + 1][1],
                        sb_l + boff[p] + kb);
#pragma unroll
            for (int mb = 0; mb < 2; mb++)
#pragma unroll
                for (int nb = 0; nb < 8; nb++) mma_bf16(acc[mb][nb], ahf[mb], bfr[nb]);
        }
        __syncthreads();
    }

    // ---- epilogue: c frag (r = lane>>2, c = 2*(lane&3)); rows +0/+8 ----
    int crow0 = m0 + warp_m * 32 + (lane >> 2);
    int ccol0 = n0 + warp_n * 64 + 2 * (lane & 3);
#pragma unroll
    for (int mb = 0; mb < 2; mb++) {
#pragma unroll
        for (int nb = 0; nb < 8; nb++) {
            int colg = ccol0 + nb * 8;
            if (colg < M) {
                int r0 = crow0 + mb * 16;
                if (r0 < NN)
                    *reinterpret_cast<float2*>(C + (size_t)r0 * M + colg) =
                        make_float2(acc[mb][nb][0], acc[mb][nb][1]);
                int r1 = r0 + 8;
                if (r1 < NN)
                    *reinterpret_cast<float2*>(C + (size_t)r1 * M + colg) =
                        make_float2(acc[mb][nb][2], acc[mb][nb][3]);
            }
        }
    }
}

// ---------------- el/er projections: warp per node ----------------
template <int HD, int D>
__global__ void eler_k(const float* __restrict__ feat, const float* __restrict__ al,
                       const float* __restrict__ ar, float* __restrict__ el,
                       float* __restrict__ er) {
    int w = (blockIdx.x * blockDim.x + threadIdx.x) >> 5;
    int lane = threadIdx.x & 31;
    if (w >= NN) return;
    const float* f = feat + (size_t)w * HD;
    float a0 = 0, a1 = 0, a2 = 0, a3 = 0, b0 = 0, b1 = 0, b2 = 0, b3 = 0;
    constexpr int P = (HD + 31) / 32;
#pragma unroll
    for (int p = 0; p < P; p++) {
        int idx = lane + 32 * p;
        if ((HD % 32 == 0) || idx < HD) {
            float v = f[idx];
            float pl = v * al[idx];
            float pr = v * ar[idx];
            int h = (D % 32 == 0) ? ((32 * p) / D) : (idx / D);
            if (h == 0)      { a0 += pl; b0 += pr; }
            else if (h == 1) { a1 += pl; b1 += pr; }
            else if (h == 2) { a2 += pl; b2 += pr; }
            else             { a3 += pl; b3 += pr; }
        }
    }
#pragma unroll
    for (int o = 16; o; o >>= 1) {
        a0 += __shfl_xor_sync(0xffffffffu, a0, o);
        a1 += __shfl_xor_sync(0xffffffffu, a1, o);
        a2 += __shfl_xor_sync(0xffffffffu, a2, o);
        a3 += __shfl_xor_sync(0xffffffffu, a3, o);
        b0 += __shfl_xor_sync(0xffffffffu, b0, o);
        b1 += __shfl_xor_sync(0xffffffffu, b1, o);
        b2 += __shfl_xor_sync(0xffffffffu, b2, o);
        b3 += __shfl_xor_sync(0xffffffffu, b3, o);
    }
    if (lane == 0) {
        el[w * 4 + 0] = a0; el[w * 4 + 1] = a1; el[w * 4 + 2] = a2; el[w * 4 + 3] = a3;
        er[w * 4 + 0] = b0; er[w * 4 + 1] = b1; er[w * 4 + 2] = b2; er[w * 4 + 3] = b3;
    }
}

__device__ __forceinline__ float lrelu(float e) { return e > 0.f ? e : 0.2f * e; }

// ---------------- aggregate layers 1/2: warp per node, H=4, D=64, ELU ----------------
__global__ void aggregate_h64_k(const float* __restrict__ feat,
                                const int* __restrict__ rowptr, const int* __restrict__ col,
                                const float* __restrict__ el, const float* __restrict__ er,
                                float* __restrict__ ealpha, float* __restrict__ out) {
    int n = (blockIdx.x * blockDim.x + threadIdx.x) >> 5;
    int lane = threadIdx.x & 31;
    if (n >= NN) return;
    int beg = rowptr[n], end = rowptr[n + 1];
    float er0 = er[n * 4 + 0], er1 = er[n * 4 + 1], er2 = er[n * 4 + 2], er3 = er[n * 4 + 3];
    float m0 = -INFINITY, m1 = -INFINITY, m2 = -INFINITY, m3 = -INFINITY;
    for (int j = beg + lane; j < end; j += 32) {
        int s = col[j];
        m0 = fmaxf(m0, lrelu(el[s * 4 + 0] + er0));
        m1 = fmaxf(m1, lrelu(el[s * 4 + 1] + er1));
        m2 = fmaxf(m2, lrelu(el[s * 4 + 2] + er2));
        m3 = fmaxf(m3, lrelu(el[s * 4 + 3] + er3));
    }
#pragma unroll
    for (int o = 16; o; o >>= 1) {
        m0 = fmaxf(m0, __shfl_xor_sync(0xffffffffu, m0, o));
        m1 = fmaxf(m1, __shfl_xor_sync(0xffffffffu, m1, o));
        m2 = fmaxf(m2, __shfl_xor_sync(0xffffffffu, m2, o));
        m3 = fmaxf(m3, __shfl_xor_sync(0xffffffffu, m3, o));
    }
    float s0 = 0, s1 = 0, s2 = 0, s3 = 0;
    for (int j = beg + lane; j < end; j += 32) {
        int s = col[j];
        float x0 = __expf(lrelu(el[s * 4 + 0] + er0) - m0);
        float x1 = __expf(lrelu(el[s * 4 + 1] + er1) - m1);
        float x2 = __expf(lrelu(el[s * 4 + 2] + er2) - m2);
        float x3 = __expf(lrelu(el[s * 4 + 3] + er3) - m3);
        ealpha[j * 4 + 0] = x0; ealpha[j * 4 + 1] = x1;
        ealpha[j * 4 + 2] = x2; ealpha[j * 4 + 3] = x3;
        s0 += x0; s1 += x1; s2 += x2; s3 += x3;
    }
#pragma unroll
    for (int o = 16; o; o >>= 1) {
        s0 += __shfl_xor_sync(0xffffffffu, s0, o);
        s1 += __shfl_xor_sync(0xffffffffu, s1, o);
        s2 += __shfl_xor_sync(0xffffffffu, s2, o);
        s3 += __shfl_xor_sync(0xffffffffu, s3, o);
    }
    float i0 = s0 > 0.f ? 1.f / s0 : 0.f;
    float i1 = s1 > 0.f ? 1.f / s1 : 0.f;
    float i2 = s2 > 0.f ? 1.f / s2 : 0.f;
    float i3 = s3 > 0.f ? 1.f / s3 : 0.f;
    float acc[8];
#pragma unroll
    for (int p = 0; p < 8; p++) acc[p] = 0.f;
    for (int j = beg; j < end; j++) {
        int s = col[j];  // uniform across warp
        const float* f = feat + (size_t)s * 256;
        float a0 = ealpha[j * 4 + 0] * i0;
        float a1 = ealpha[j * 4 + 1] * i1;
        float a2 = ealpha[j * 4 + 2] * i2;
        float a3 = ealpha[j * 4 + 3] * i3;
        acc[0] = fmaf(a0, f[lane +   0], acc[0]);
        acc[1] = fmaf(a0, f[lane +  32], acc[1]);
        acc[2] = fmaf(a1, f[lane +  64], acc[2]);
        acc[3] = fmaf(a1, f[lane +  96], acc[3]);
        acc[4] = fmaf(a2, f[lane + 128], acc[4]);
        acc[5] = fmaf(a2, f[lane + 160], acc[5]);
        acc[6] = fmaf(a3, f[lane + 192], acc[6]);
        acc[7] = fmaf(a3, f[lane + 224], acc[7]);
    }
#pragma unroll
    for (int p = 0; p < 8; p++) {
        float v = acc[p];
        v = v > 0.f ? v : (__expf(v) - 1.f);  // ELU
        out[(size_t)n * 256 + lane + 32 * p] = v;
    }
}

// ---------------- aggregate output layer: H=4, D=121, mean over heads ----------------
__global__ void aggregate_out_k(const float* __restrict__ feat,
                                const int* __restrict__ rowptr, const int* __restrict__ col,
                                const float* __restrict__ el, const float* __restrict__ er,
                                float* __restrict__ ealpha, float* __restrict__ out) {
    int n = (blockIdx.x * blockDim.x + threadIdx.x) >> 5;
    int lane = threadIdx.x & 31;
    if (n >= NN) return;
    int beg = rowptr[n], end = rowptr[n + 1];
    float er0 = er[n * 4 + 0], er1 = er[n * 4 + 1], er2 = er[n * 4 + 2], er3 = er[n * 4 + 3];
    float m0 = -INFINITY, m1 = -INFINITY, m2 = -INFINITY, m3 = -INFINITY;
    for (int j = beg + lane; j < end; j += 32) {
        int s = col[j];
        m0 = fmaxf(m0, lrelu(el[s * 4 + 0] + er0));
        m1 = fmaxf(m1, lrelu(el[s * 4 + 1] + er1));
        m2 = fmaxf(m2, lrelu(el[s * 4 + 2] + er2));
        m3 = fmaxf(m3, lrelu(el[s * 4 + 3] + er3));
    }
#pragma unroll
    for (int o = 16; o; o >>= 1) {
        m0 = fmaxf(m0, __shfl_xor_sync(0xffffffffu, m0, o));
        m1 = fmaxf(m1, __shfl_xor_sync(0xffffffffu, m1, o));
        m2 = fmaxf(m2, __shfl_xor_sync(0xffffffffu, m2, o));
        m3 = fmaxf(m3, __shfl_xor_sync(0xffffffffu, m3, o));
    }
    float s0 = 0, s1 = 0, s2 = 0, s3 = 0;
    for (int j = beg + lane; j < end; j += 32) {
        int s = col[j];
        float x0 = __expf(lrelu(el[s * 4 + 0] + er0) - m0);
        float x1 = __expf(lrelu(el[s * 4 + 1] + er1) - m1);
        float x2 = __expf(lrelu(el[s * 4 + 2] + er2) - m2);
        float x3 = __expf(lrelu(el[s * 4 + 3] + er3) - m3);
        ealpha[j * 4 + 0] = x0; ealpha[j * 4 + 1] = x1;
        ealpha[j * 4 + 2] = x2; ealpha[j * 4 + 3] = x3;
        s0 += x0; s1 += x1; s2 += x2; s3 += x3;
    }
#pragma unroll
    for (int o = 16; o; o >>= 1) {
        s0 += __shfl_xor_sync(0xffffffffu, s0, o);
        s1 += __shfl_xor_sync(0xffffffffu, s1, o);
        s2 += __shfl_xor_sync(0xffffffffu, s2, o);
        s3 += __shfl_xor_sync(0xffffffffu, s3, o);
    }
    float i0 = s0 > 0.f ? 1.f / s0 : 0.f;
    float i1 = s1 > 0.f ? 1.f / s1 : 0.f;
    float i2 = s2 > 0.f ? 1.f / s2 : 0.f;
    float i3 = s3 > 0.f ? 1.f / s3 : 0.f;
    float acc0 = 0, acc1 = 0, acc2 = 0, acc3 = 0;
    int c0 = lane, c1 = lane + 32, c2 = lane + 64, c3 = lane + 96;
    for (int j = beg; j < end; j++) {
        int s = col[j];  // uniform across warp
        const float* f = feat + (size_t)s * 484;
        float a0 = ealpha[j * 4 + 0] * i0;
        float a1 = ealpha[j * 4 + 1] * i1;
        float a2 = ealpha[j * 4 + 2] * i2;
        float a3 = ealpha[j * 4 + 3] * i3;
#pragma unroll
        for (int h = 0; h < 4; h++) {
            float ahh = (h == 0) ? a0 : (h == 1) ? a1 : (h == 2) ? a2 : a3;
            const float* fh = f + h * 121;
            acc0 = fmaf(ahh, fh[c0], acc0);
            acc1 = fmaf(ahh, fh[c1], acc1);
            acc2 = fmaf(ahh, fh[c2], acc2);
            if (c3 < 121) acc3 = fmaf(ahh, fh[c3], acc3);
        }
    }
    out[(size_t)n * 121 + c0] = acc0 * 0.25f;
    out[(size_t)n * 121 + c1] = acc1 * 0.25f;
    out[(size_t)n * 121 + c2] = acc2 * 0.25f;
    if (c3 < 121) out[(size_t)n * 121 + c3] = acc3 * 0.25f;
}

// ---------------- host launch ----------------
extern "C" void kernel_launch(void* const* d_in, const int* in_sizes, int n_in,
                              void* d_out, int out_size) {
    const float* h   = (const float*)d_in[0];
    const int*   src = (const int*)d_in[1];
    const int*   dst = (const int*)d_in[2];
    const float* W1  = (const float*)d_in[3];
    const float* al1 = (const float*)d_in[4];
    const float* ar1 = (const float*)d_in[5];
    const float* W2  = (const float*)d_in[6];
    const float* al2 = (const float*)d_in[7];
    const float* ar2 = (const float*)d_in[8];
    const float* W3  = (const float*)d_in[9];
    const float* al3 = (const float*)d_in[10];
    const float* ar3 = (const float*)d_in[11];
    float* out = (float*)d_out;

    float *feat, *x, *el, *er, *ealpha;
    int *deg, *wp, *rowptr, *col;
    __nv_bfloat16 *ah, *al, *bh, *bl;
    cudaGetSymbolAddress((void**)&feat,   g_feat);
    cudaGetSymbolAddress((void**)&x,      g_x);
    cudaGetSymbolAddress((void**)&el,     g_el);
    cudaGetSymbolAddress((void**)&er,     g_er);
    cudaGetSymbolAddress((void**)&ealpha, g_ealpha);
    cudaGetSymbolAddress((void**)&deg,    g_deg);
    cudaGetSymbolAddress((void**)&wp,     g_wp);
    cudaGetSymbolAddress((void**)&rowptr, g_rowptr);
    cudaGetSymbolAddress((void**)&col,    g_col);
    cudaGetSymbolAddress((void**)&ah,     g_ah);
    cudaGetSymbolAddress((void**)&al,     g_al);
    cudaGetSymbolAddress((void**)&bh,     g_bh);
    cudaGetSymbolAddress((void**)&bl,     g_bl);

    // CSR build (graph identical for all 3 layers)
    zero_deg_k<<<(NN + 255) / 256, 256>>>(deg);
    hist_k<<<512, 256>>>(dst, deg);
    scan_k<<<1, 1024>>>(deg, rowptr, wp);
    scatter_k<<<512, 256>>>(src, dst, wp, col);

    int wblocks = (NN + 7) / 8;
    const int ATOT = NN * 256;
    dim3 gemm_grid2(2, (NN + 127) / 128);   // N=256
    dim3 gemm_grid4(4, (NN + 127) / 128);   // Npad=512

    // layer 1
    cvt_a_k<<<(ATOT + 255) / 256, 256>>>(h, ah, al, ATOT);
    cvt_w_k<<<(256 * 256 + 255) / 256, 256>>>(W1, bh, bl, 256, 256);
    gemm_hmma_k<<<gemm_grid2, 256>>>(ah, al, bh, bl, feat, 256);
    eler_k<256, 64><<<wblocks, 256>>>(feat, al1, ar1, el, er);
    aggregate_h64_k<<<wblocks, 256>>>(feat, rowptr, col, el, er, ealpha, x);

    // layer 2
    cvt_a_k<<<(ATOT + 255) / 256, 256>>>(x, ah, al, ATOT);
    cvt_w_k<<<(256 * 256 + 255) / 256, 256>>>(W2, bh, bl, 256, 256);
    gemm_hmma_k<<<gemm_grid2, 256>>>(ah, al, bh, bl, feat, 256);
    eler_k<256, 64><<<wblocks, 256>>>(feat, al2, ar2, el, er);
    aggregate_h64_k<<<wblocks, 256>>>(feat, rowptr, col, el, er, ealpha, x);

    // layer 3 (output): M = 484, Npad = 512
    cvt_a_k<<<(ATOT + 255) / 256, 256>>>(x, ah, al, ATOT);
    cvt_w_k<<<(512 * 256 + 255) / 256, 256>>>(W3, bh, bl, 484, 512);
    gemm_hmma_k<<<gemm_grid4, 256>>>(ah, al, bh, bl, feat, 484);
    eler_k<484, 121><<<wblocks, 256>>>(feat, al3, ar3, el, er);
    aggregate_out_k<<<wblocks, 256>>>(feat, rowptr, col, el, er, ealpha, out);
}